// round 1
// baseline (speedup 1.0000x reference)
#include <cuda_runtime.h>
#include <math.h>

#define BATCH 32
#define NN    512
#define NF    256
#define NH    8
#define ND    64
#define HDIM  512   // NH*ND
#define NO    128
#define ALPHA 0.2f
#define ACVT  0.01f

// ---------------- scratch (static device globals; no allocation) -------------
__device__ float g_h  [BATCH*NH*NN*ND];        // h[b][h][n][d]
__device__ float g_se1[BATCH*NH*NN];           // sorted e1
__device__ float g_us [BATCH*NH*NN];           // exp(e1 - m1), sorted order
__device__ float g_ups[BATCH*NH*NN];           // exp(a*e1 - m1), sorted order
__device__ int   g_perm[BATCH*NH*NN];
__device__ float g_e2 [BATCH*NH*NN];
__device__ float g_v  [BATCH*NH*NN];           // exp(e2 - m2)
__device__ float g_vp [BATCH*NH*NN];           // exp(a*e2 - m2)
__device__ float g_A  [BATCH*NH*(NN+1)*ND];    // prefix  sum of u' * h
__device__ float g_Bx [BATCH*NH*(NN+1)*ND];    // suffix  sum of u  * h
__device__ float g_QA [BATCH*NH*(NN+1)];
__device__ float g_QB [BATCH*NH*(NN+1)];
__device__ float g_x2 [BATCH*NN*HDIM];
__device__ float g_h2 [BATCH*NN*NO];
__device__ float g_f1 [BATCH*NN];
__device__ float g_f2 [BATCH*NN];

// ---------------- generic NT GEMM: C[M,N] = A[M,K] * B[N,K]^T ----------------
// MODE 0: A,B args; write into g_h with [b][h][n][d] layout
// MODE 2: A = g_x2, B arg; write g_h2 row-major [M, N]
template<int MODE>
__global__ __launch_bounds__(256) void gemm_nt(const float* __restrict__ A,
                                               const float* __restrict__ B,
                                               int M, int N, int K)
{
    __shared__ float As[16][132];
    __shared__ float Bs[16][132];
    const float* Ap = (MODE == 2) ? g_x2 : A;
    const int tid = threadIdx.x;
    const int bm  = blockIdx.y * 128;
    const int bn  = blockIdx.x * 128;
    const int tm  = (tid >> 4) * 8;
    const int tn  = (tid & 15) * 8;

    float acc[8][8];
#pragma unroll
    for (int i = 0; i < 8; i++)
#pragma unroll
        for (int j = 0; j < 8; j++) acc[i][j] = 0.f;

    for (int k0 = 0; k0 < K; k0 += 16) {
#pragma unroll
        for (int q = 0; q < 2; q++) {
            int f4 = tid + q * 256;       // 0..511
            int r  = f4 >> 2;             // 0..127
            int c  = (f4 & 3) * 4;        // 0,4,8,12
            float4 va = *(const float4*)(Ap + (size_t)(bm + r) * K + k0 + c);
            As[c+0][r] = va.x; As[c+1][r] = va.y; As[c+2][r] = va.z; As[c+3][r] = va.w;
            float4 vb = *(const float4*)(B + (size_t)(bn + r) * K + k0 + c);
            Bs[c+0][r] = vb.x; Bs[c+1][r] = vb.y; Bs[c+2][r] = vb.z; Bs[c+3][r] = vb.w;
        }
        __syncthreads();
#pragma unroll
        for (int k = 0; k < 16; k++) {
            float a[8], bb[8];
#pragma unroll
            for (int i = 0; i < 8; i++) a[i]  = As[k][tm + i];
#pragma unroll
            for (int j = 0; j < 8; j++) bb[j] = Bs[k][tn + j];
#pragma unroll
            for (int i = 0; i < 8; i++)
#pragma unroll
                for (int j = 0; j < 8; j++)
                    acc[i][j] = fmaf(a[i], bb[j], acc[i][j]);
        }
        __syncthreads();
    }

#pragma unroll
    for (int i = 0; i < 8; i++) {
        int row = bm + tm + i;
#pragma unroll
        for (int j = 0; j < 8; j++) {
            int col = bn + tn + j;
            if (MODE == 0) {
                int b = row >> 9, n = row & 511, hh = col >> 6, d = col & 63;
                g_h[(((size_t)(b * NH + hh)) * NN + n) * ND + d] = acc[i][j];
            } else {
                g_h2[(size_t)row * N + col] = acc[i][j];
            }
        }
    }
}

// -------- K2: e1,e2 per (b,h); max; bitonic sort of e1; exp factor tables ----
__global__ __launch_bounds__(256) void k2_attn_prep(const float* __restrict__ a1,
                                                    const float* __restrict__ a2)
{
    int bh  = blockIdx.x;     // 0..255
    int h   = bh & 7;
    int tid = threadIdx.x;
    __shared__ float a1s[ND], a2s[ND];
    __shared__ float e2s[NN];
    __shared__ float skey[NN];
    __shared__ int   sidx[NN];
    __shared__ float red[256];

    if (tid < ND) { a1s[tid] = a1[h * ND + tid]; a2s[tid] = a2[h * ND + tid]; }
    __syncthreads();

    const float* hb = g_h + (size_t)bh * NN * ND;
#pragma unroll
    for (int q = 0; q < 2; q++) {
        int n = tid + q * 256;
        const float4* hr = (const float4*)(hb + (size_t)n * ND);
        float s1 = 0.f, s2 = 0.f;
#pragma unroll
        for (int i = 0; i < 16; i++) {
            float4 v = hr[i];
            s1 += v.x*a1s[4*i] + v.y*a1s[4*i+1] + v.z*a1s[4*i+2] + v.w*a1s[4*i+3];
            s2 += v.x*a2s[4*i] + v.y*a2s[4*i+1] + v.z*a2s[4*i+2] + v.w*a2s[4*i+3];
        }
        skey[n] = s1; sidx[n] = n; e2s[n] = s2;
    }
    __syncthreads();

    // max of e2
    red[tid] = fmaxf(e2s[tid], e2s[tid + 256]);
    __syncthreads();
    for (int s = 128; s > 0; s >>= 1) {
        if (tid < s) red[tid] = fmaxf(red[tid], red[tid + s]);
        __syncthreads();
    }
    float m2 = red[0];

    // bitonic sort ascending (key=e1, payload=index)
    for (int ksz = 2; ksz <= NN; ksz <<= 1) {
        for (int j = ksz >> 1; j > 0; j >>= 1) {
            __syncthreads();
#pragma unroll
            for (int q = 0; q < 2; q++) {
                int i   = tid + q * 256;
                int ixj = i ^ j;
                if (ixj > i) {
                    bool up = ((i & ksz) == 0);
                    float ki = skey[i], kj = skey[ixj];
                    if ((ki > kj) == up) {
                        skey[i] = kj; skey[ixj] = ki;
                        int t = sidx[i]; sidx[i] = sidx[ixj]; sidx[ixj] = t;
                    }
                }
            }
        }
    }
    __syncthreads();

    float m1 = skey[NN - 1];  // sorted ascending
    size_t o = (size_t)bh * NN;
#pragma unroll
    for (int q = 0; q < 2; q++) {
        int t = tid + q * 256;
        float k = skey[t];
        g_se1[o + t]  = k;
        g_us [o + t]  = __expf(k - m1);
        g_ups[o + t]  = __expf(ALPHA * k - m1);
        g_perm[o + t] = sidx[t];
        float e2 = e2s[t];
        g_e2[o + t] = e2;
        g_v [o + t] = __expf(e2 - m2);
        g_vp[o + t] = __expf(ALPHA * e2 - m2);
    }
}

// -------- K3b: prefix (u'*h) and suffix (u*h) sums along sorted e1 ----------
__global__ __launch_bounds__(128) void k3b_prefix()
{
    int bh  = blockIdx.x;
    int tid = threadIdx.x;
    size_t o  = (size_t)bh * NN;
    size_t oa = (size_t)bh * (NN + 1) * ND;
    size_t oq = (size_t)bh * (NN + 1);
    const float* hb = g_h + (size_t)bh * NN * ND;

    if (tid < 64) {
        int d = tid;
        float acc = 0.f, q = 0.f;
        for (int t = 0; t < NN; t++) {
            g_A[oa + (size_t)t * ND + d] = acc;
            if (d == 0) g_QA[oq + t] = q;
            int   p = g_perm[o + t];
            float w = g_ups[o + t];
            acc = fmaf(w, hb[(size_t)p * ND + d], acc);
            q  += w;
        }
        g_A[oa + (size_t)NN * ND + d] = acc;
        if (d == 0) g_QA[oq + NN] = q;
    } else {
        int d = tid - 64;
        float acc = 0.f, q = 0.f;
        g_Bx[oa + (size_t)NN * ND + d] = 0.f;
        if (d == 0) g_QB[oq + NN] = 0.f;
        for (int t = NN - 1; t >= 0; t--) {
            int   p = g_perm[o + t];
            float w = g_us[o + t];
            acc = fmaf(w, hb[(size_t)p * ND + d], acc);
            q  += w;
            g_Bx[oa + (size_t)t * ND + d] = acc;
            if (d == 0) g_QB[oq + t] = q;
        }
    }
}

// -------- K3c: per row j, binary-search split, combine, acvt leaky -> x2 ----
__global__ __launch_bounds__(256) void k3c_apply()
{
    int bh = blockIdx.x;
    int b = bh >> 3, h = bh & 7;
    int tid  = threadIdx.x;
    int lane = tid & 31, wid = tid >> 5;
    __shared__ float se1[NN];
    __shared__ float qa[NN + 1], qb[NN + 1];
    size_t o  = (size_t)bh * NN;
    size_t oa = (size_t)bh * (NN + 1) * ND;
    size_t oq = (size_t)bh * (NN + 1);

    for (int i = tid; i < NN; i += 256) se1[i] = g_se1[o + i];
    for (int i = tid; i < NN + 1; i += 256) { qa[i] = g_QA[oq + i]; qb[i] = g_QB[oq + i]; }
    __syncthreads();

    for (int j = wid * 64; j < wid * 64 + 64; j++) {
        float e2 = g_e2[o + j];
        float v  = g_v [o + j];
        float vp = g_vp[o + j];
        float target = -e2;
        int lo = 0, hi = NN;
        while (lo < hi) { int mid = (lo + hi) >> 1; if (se1[mid] < target) lo = mid + 1; else hi = mid; }
        int t = lo;   // [0,t): branch s<0 (prefix, u',v'); [t,NN): branch s>=0 (suffix, u,v)
        float iz = 1.f / (vp * qa[t] + v * qb[t]);
        const float* Ar = g_A  + oa + (size_t)t * ND;
        const float* Br = g_Bx + oa + (size_t)t * ND;
        float o0 = (vp * Ar[lane]      + v * Br[lane])      * iz;
        float o1 = (vp * Ar[lane + 32] + v * Br[lane + 32]) * iz;
        o0 = (o0 >= 0.f) ? o0 : ACVT * o0;   // acvt LeakyReLU(0.01)
        o1 = (o1 >= 0.f) ? o1 : ACVT * o1;
        float* x2r = g_x2 + ((size_t)(b * NN + j) * HDIM) + h * ND;
        x2r[lane]      = o0;
        x2r[lane + 32] = o1;
    }
}

// -------- K5: f1 = h2 @ a1_out, f2 = h2 @ a2_out -----------------------------
__global__ __launch_bounds__(512) void k5_f(const float* __restrict__ a1o,
                                            const float* __restrict__ a2o)
{
    int b = blockIdx.x, k = threadIdx.x;
    __shared__ float s1[NO], s2[NO];
    if (k < NO) { s1[k] = a1o[k]; s2[k] = a2o[k]; }
    __syncthreads();
    const float4* hr = (const float4*)(g_h2 + (size_t)(b * NN + k) * NO);
    float f1 = 0.f, f2 = 0.f;
#pragma unroll
    for (int i = 0; i < NO / 4; i++) {
        float4 v = hr[i];
        f1 += v.x*s1[4*i] + v.y*s1[4*i+1] + v.z*s1[4*i+2] + v.w*s1[4*i+3];
        f2 += v.x*s2[4*i] + v.y*s2[4*i+1] + v.z*s2[4*i+2] + v.w*s2[4*i+3];
    }
    g_f1[b * NN + k] = f1;
    g_f2[b * NN + k] = f2;
}

// -------- K6: output attention (folded with mean) + Linear + normalize -------
__global__ __launch_bounds__(512) void k6_final(const float* __restrict__ Wlin,
                                                const float* __restrict__ blin,
                                                float* __restrict__ out)
{
    int b = blockIdx.x, tid = threadIdx.x;
    __shared__ float f1s[NN], f2s[NN], ms[NN], izs[NN], ws[NN];
    __shared__ float om[NO], ys[NO], red[4];

    f1s[tid] = g_f1[b * NN + tid];
    f2s[tid] = g_f2[b * NN + tid];
    __syncthreads();

    // phase 1: per-row (j=tid) max and inv-sum
    {
        float fj = f2s[tid];
        float m = -1e30f;
        for (int k = 0; k < NN; k++) {
            float s = f1s[k] + fj;
            s = (s >= 0.f) ? s : ALPHA * s;
            m = fmaxf(m, s);
        }
        float z = 0.f;
        for (int k = 0; k < NN; k++) {
            float s = f1s[k] + fj;
            s = (s >= 0.f) ? s : ALPHA * s;
            z += __expf(s - m);
        }
        ms[tid]  = m;
        izs[tid] = 1.f / z;
    }
    __syncthreads();

    // phase 2: w[k] = (1/N) * sum_j att[j,k]
    {
        float fk = f1s[tid];
        float w = 0.f;
        for (int j = 0; j < NN; j++) {
            float s = fk + f2s[j];
            s = (s >= 0.f) ? s : ALPHA * s;
            w += __expf(s - ms[j]) * izs[j];
        }
        ws[tid] = w * (1.0f / (float)NN);
    }
    __syncthreads();

    // phase 3: out_mean[d] = sum_k w[k] * h2[b,k,d]
    if (tid < NO) {
        float s = 0.f;
        for (int k = 0; k < NN; k++)
            s = fmaf(ws[k], g_h2[(size_t)(b * NN + k) * NO + tid], s);
        om[tid] = s;
    }
    __syncthreads();

    // phase 4: linear
    if (tid < NO) {
        float y = blin[tid];
        const float* wr = Wlin + (size_t)tid * NO;
        for (int d = 0; d < NO; d++) y = fmaf(om[d], wr[d], y);
        ys[tid] = y;
    }
    __syncthreads();

    // phase 5: L2 normalize
    if (tid < NO) {
        float v = ys[tid] * ys[tid];
#pragma unroll
        for (int s = 16; s > 0; s >>= 1) v += __shfl_down_sync(0xffffffffu, v, s);
        if ((tid & 31) == 0) red[tid >> 5] = v;
    }
    __syncthreads();
    if (tid == 0) {
        float s = red[0] + red[1] + red[2] + red[3];
        red[0] = fmaxf(sqrtf(s), 1e-12f);
    }
    __syncthreads();
    if (tid < NO) out[b * NO + tid] = ys[tid] / red[0];
}

// -----------------------------------------------------------------------------
extern "C" void kernel_launch(void* const* d_in, const int* in_sizes, int n_in,
                              void* d_out, int out_size)
{
    (void)in_sizes; (void)n_in; (void)out_size;
    const float* X    = (const float*)d_in[0];  // [32,512,256]
    const float* Wt   = (const float*)d_in[1];  // [8,64,256] -> flat [512,256]
    const float* a1   = (const float*)d_in[2];  // [8,64]
    const float* a2   = (const float*)d_in[3];  // [8,64]
    const float* Wout = (const float*)d_in[4];  // [128,512]
    const float* a1o  = (const float*)d_in[5];  // [128]
    const float* a2o  = (const float*)d_in[6];  // [128]
    const float* Wlin = (const float*)d_in[7];  // [128,128]
    const float* blin = (const float*)d_in[8];  // [128]
    float* out = (float*)d_out;                 // [32,128]

    // K1: h = X @ Wt^T   (M=16384, N=512, K=256) -> g_h[b][h][n][d]
    gemm_nt<0><<<dim3(HDIM / 128, (BATCH * NN) / 128), 256>>>(X, Wt, BATCH * NN, HDIM, NF);
    // K2: e1/e2, sort e1, exp factor tables
    k2_attn_prep<<<BATCH * NH, 256>>>(a1, a2);
    // K3b: prefix/suffix weighted sums
    k3b_prefix<<<BATCH * NH, 128>>>();
    // K3c: per-row combine + acvt -> x2
    k3c_apply<<<BATCH * NH, 256>>>();
    // K4: h2 = x2 @ Wout^T (M=16384, N=128, K=512)
    gemm_nt<2><<<dim3(NO / 128, (BATCH * NN) / 128), 256>>>(nullptr, Wout, BATCH * NN, NO, HDIM);
    // K5: f1/f2
    k5_f<<<BATCH, 512>>>(a1o, a2o);
    // K6: output attention + mean + linear + normalize
    k6_final<<<BATCH, 512>>>(Wlin, blin, out);
}

// round 2
// speedup vs baseline: 1.4232x; 1.4232x over previous
#include <cuda_runtime.h>
#include <math.h>

#define BATCH 32
#define NN    512
#define NF    256
#define NH    8
#define ND    64
#define HDIM  512   // NH*ND
#define NO    128
#define ALPHA 0.2f
#define ACVT  0.01f

// ---------------- scratch (static device globals; no allocation) -------------
__device__ float g_h  [BATCH*NH*NN*ND];        // h[b][h][n][d]
__device__ float g_se1[BATCH*NH*NN];           // sorted e1
__device__ float g_us [BATCH*NH*NN];           // exp(e1 - m1), sorted order
__device__ float g_ups[BATCH*NH*NN];           // exp(a*e1 - m1), sorted order
__device__ int   g_perm[BATCH*NH*NN];
__device__ float g_e2 [BATCH*NH*NN];
__device__ float g_v  [BATCH*NH*NN];           // exp(e2 - m2)
__device__ float g_vp [BATCH*NH*NN];           // exp(a*e2 - m2)
__device__ float g_A  [BATCH*NH*(NN+1)*ND];    // exclusive prefix of u' * h
__device__ float g_Bx [BATCH*NH*(NN+1)*ND];    // inclusive suffix of u  * h
__device__ float g_QA [BATCH*NH*(NN+1)];
__device__ float g_QB [BATCH*NH*(NN+1)];
__device__ float g_x2 [BATCH*NN*HDIM];
__device__ float g_h2 [BATCH*NN*NO];
__device__ float g_f1 [BATCH*NN];
__device__ float g_f2 [BATCH*NN];
__device__ float g_maxf1[BATCH];
__device__ float g_ms [BATCH*NN];
__device__ float g_izv[BATCH*NN];
__device__ float g_w  [BATCH*NN];

// ---------------- generic NT GEMM: C[M,N] = A[M,K] * B[N,K]^T ----------------
template<int MODE>
__global__ __launch_bounds__(256) void gemm_nt(const float* __restrict__ A,
                                               const float* __restrict__ B,
                                               int M, int N, int K)
{
    __shared__ float As[16][132];
    __shared__ float Bs[16][132];
    const float* Ap = (MODE == 2) ? g_x2 : A;
    const int tid = threadIdx.x;
    const int bm  = blockIdx.y * 128;
    const int bn  = blockIdx.x * 128;
    const int tm  = (tid >> 4) * 8;
    const int tn  = (tid & 15) * 8;

    float acc[8][8];
#pragma unroll
    for (int i = 0; i < 8; i++)
#pragma unroll
        for (int j = 0; j < 8; j++) acc[i][j] = 0.f;

    for (int k0 = 0; k0 < K; k0 += 16) {
#pragma unroll
        for (int q = 0; q < 2; q++) {
            int f4 = tid + q * 256;
            int r  = f4 >> 2;
            int c  = (f4 & 3) * 4;
            float4 va = *(const float4*)(Ap + (size_t)(bm + r) * K + k0 + c);
            As[c+0][r] = va.x; As[c+1][r] = va.y; As[c+2][r] = va.z; As[c+3][r] = va.w;
            float4 vb = *(const float4*)(B + (size_t)(bn + r) * K + k0 + c);
            Bs[c+0][r] = vb.x; Bs[c+1][r] = vb.y; Bs[c+2][r] = vb.z; Bs[c+3][r] = vb.w;
        }
        __syncthreads();
#pragma unroll
        for (int k = 0; k < 16; k++) {
            float a[8], bb[8];
#pragma unroll
            for (int i = 0; i < 8; i++) a[i]  = As[k][tm + i];
#pragma unroll
            for (int j = 0; j < 8; j++) bb[j] = Bs[k][tn + j];
#pragma unroll
            for (int i = 0; i < 8; i++)
#pragma unroll
                for (int j = 0; j < 8; j++)
                    acc[i][j] = fmaf(a[i], bb[j], acc[i][j]);
        }
        __syncthreads();
    }

#pragma unroll
    for (int i = 0; i < 8; i++) {
        int row = bm + tm + i;
#pragma unroll
        for (int j = 0; j < 8; j++) {
            int col = bn + tn + j;
            if (MODE == 0) {
                int b = row >> 9, n = row & 511, hh = col >> 6, d = col & 63;
                g_h[(((size_t)(b * NH + hh)) * NN + n) * ND + d] = acc[i][j];
            } else {
                g_h2[(size_t)row * N + col] = acc[i][j];
            }
        }
    }
}

// -------- K2: e1,e2 per (b,h); max; bitonic sort of e1; exp factor tables ----
__global__ __launch_bounds__(256) void k2_attn_prep(const float* __restrict__ a1,
                                                    const float* __restrict__ a2)
{
    int bh  = blockIdx.x;
    int h   = bh & 7;
    int tid = threadIdx.x;
    __shared__ float a1s[ND], a2s[ND];
    __shared__ float e2s[NN];
    __shared__ float skey[NN];
    __shared__ int   sidx[NN];
    __shared__ float red[256];

    if (tid < ND) { a1s[tid] = a1[h * ND + tid]; a2s[tid] = a2[h * ND + tid]; }
    __syncthreads();

    const float* hb = g_h + (size_t)bh * NN * ND;
#pragma unroll
    for (int q = 0; q < 2; q++) {
        int n = tid + q * 256;
        const float4* hr = (const float4*)(hb + (size_t)n * ND);
        float s1 = 0.f, s2 = 0.f;
#pragma unroll
        for (int i = 0; i < 16; i++) {
            float4 v = hr[i];
            s1 += v.x*a1s[4*i] + v.y*a1s[4*i+1] + v.z*a1s[4*i+2] + v.w*a1s[4*i+3];
            s2 += v.x*a2s[4*i] + v.y*a2s[4*i+1] + v.z*a2s[4*i+2] + v.w*a2s[4*i+3];
        }
        skey[n] = s1; sidx[n] = n; e2s[n] = s2;
    }
    __syncthreads();

    red[tid] = fmaxf(e2s[tid], e2s[tid + 256]);
    __syncthreads();
    for (int s = 128; s > 0; s >>= 1) {
        if (tid < s) red[tid] = fmaxf(red[tid], red[tid + s]);
        __syncthreads();
    }
    float m2 = red[0];

    for (int ksz = 2; ksz <= NN; ksz <<= 1) {
        for (int j = ksz >> 1; j > 0; j >>= 1) {
            __syncthreads();
#pragma unroll
            for (int q = 0; q < 2; q++) {
                int i   = tid + q * 256;
                int ixj = i ^ j;
                if (ixj > i) {
                    bool up = ((i & ksz) == 0);
                    float ki = skey[i], kj = skey[ixj];
                    if ((ki > kj) == up) {
                        skey[i] = kj; skey[ixj] = ki;
                        int t = sidx[i]; sidx[i] = sidx[ixj]; sidx[ixj] = t;
                    }
                }
            }
        }
    }
    __syncthreads();

    float m1 = skey[NN - 1];
    size_t o = (size_t)bh * NN;
#pragma unroll
    for (int q = 0; q < 2; q++) {
        int t = tid + q * 256;
        float k = skey[t];
        g_se1[o + t]  = k;
        g_us [o + t]  = __expf(k - m1);
        g_ups[o + t]  = __expf(ALPHA * k - m1);
        g_perm[o + t] = sidx[t];
        float e2 = e2s[t];
        g_e2[o + t] = e2;
        g_v [o + t] = __expf(e2 - m2);
        g_vp[o + t] = __expf(ALPHA * e2 - m2);
    }
}

// -------- K3b: segmented-parallel prefix (u'*h) / suffix (u*h) sums ----------
// 512 threads = 64 dims x 8 segments of 64 steps each.
__global__ __launch_bounds__(512) void k3b_prefix()
{
    int bh  = blockIdx.x;
    int tid = threadIdx.x;
    int d   = tid & 63;
    int s   = tid >> 6;                 // 0..7
    size_t o  = (size_t)bh * NN;
    size_t oa = (size_t)bh * (NN + 1) * ND;
    size_t oq = (size_t)bh * (NN + 1);
    const float* hb = g_h + (size_t)bh * NN * ND;

    __shared__ float sups[NN], sus[NN];
    __shared__ int   sperm[NN];
    __shared__ float segA[8][64], segB[8][64];
    __shared__ float segQA[8], segQB[8];

    sups[tid]  = g_ups[o + tid];
    sus[tid]   = g_us [o + tid];
    sperm[tid] = g_perm[o + tid];
    __syncthreads();

    const int t0 = s * 64;

    // pass 1: per-segment totals
    float fa = 0.f, fb = 0.f, qa = 0.f, qb = 0.f;
#pragma unroll 8
    for (int i = 0; i < 64; i++) {
        int t = t0 + i;
        float hv = hb[(size_t)sperm[t] * ND + d];
        fa = fmaf(sups[t], hv, fa);
        fb = fmaf(sus[t],  hv, fb);
        qa += sups[t];
        qb += sus[t];
    }
    segA[s][d] = fa; segB[s][d] = fb;
    if (d == 0) { segQA[s] = qa; segQB[s] = qb; }
    __syncthreads();

    // cross-segment offsets
    float offA = 0.f, offB = 0.f, offQA = 0.f, offQB = 0.f;
#pragma unroll
    for (int s2 = 0; s2 < 8; s2++) {
        if (s2 < s) { offA += segA[s2][d]; offQA += segQA[s2]; }
        if (s2 > s) { offB += segB[s2][d]; offQB += segQB[s2]; }
    }

    // pass 2a: forward exclusive prefix (A, QA)
    {
        float accA = offA, accQA = offQA;
#pragma unroll 8
        for (int i = 0; i < 64; i++) {
            int t = t0 + i;
            g_A[oa + (size_t)t * ND + d] = accA;
            if (d == 0) g_QA[oq + t] = accQA;
            float hv = hb[(size_t)sperm[t] * ND + d];
            accA = fmaf(sups[t], hv, accA);
            accQA += sups[t];
        }
        if (s == 7) {
            g_A[oa + (size_t)NN * ND + d] = accA;
            if (d == 0) g_QA[oq + NN] = accQA;
        }
    }

    // pass 2b: backward inclusive suffix (B, QB)
    {
        float accB = offB, accQB = offQB;
#pragma unroll 8
        for (int i = 63; i >= 0; i--) {
            int t = t0 + i;
            float hv = hb[(size_t)sperm[t] * ND + d];
            accB = fmaf(sus[t], hv, accB);
            accQB += sus[t];
            g_Bx[oa + (size_t)t * ND + d] = accB;
            if (d == 0) g_QB[oq + t] = accQB;
        }
        if (s == 0) {
            g_Bx[oa + (size_t)NN * ND + d] = 0.f;
            if (d == 0) g_QB[oq + NN] = 0.f;
        }
    }
}

// -------- K3c: all binary searches in parallel, then warp-wide emission ------
__global__ __launch_bounds__(512) void k3c_apply()
{
    int bh = blockIdx.x;
    int b = bh >> 3, h = bh & 7;
    int tid  = threadIdx.x;
    int lane = tid & 31, wid = tid >> 5;   // 16 warps
    __shared__ float se1[NN];
    __shared__ float qa[NN + 1], qb[NN + 1];
    __shared__ int   tjs[NN];
    __shared__ float vjs[NN], vpjs[NN], izjs[NN];
    size_t o  = (size_t)bh * NN;
    size_t oa = (size_t)bh * (NN + 1) * ND;
    size_t oq = (size_t)bh * (NN + 1);

    se1[tid] = g_se1[o + tid];
    qa[tid]  = g_QA[oq + tid];
    qb[tid]  = g_QB[oq + tid];
    if (tid == 0) { qa[NN] = g_QA[oq + NN]; qb[NN] = g_QB[oq + NN]; }
    __syncthreads();

    // each thread: one row's binary search + scalars (512-way parallel)
    {
        int j = tid;
        float e2 = g_e2[o + j];
        float v  = g_v [o + j];
        float vp = g_vp[o + j];
        float target = -e2;
        int lo = 0, hi = NN;
        while (lo < hi) { int mid = (lo + hi) >> 1; if (se1[mid] < target) lo = mid + 1; else hi = mid; }
        tjs[j]  = lo;
        vjs[j]  = v;
        vpjs[j] = vp;
        izjs[j] = 1.f / (vp * qa[lo] + v * qb[lo]);
    }
    __syncthreads();

    // emission: 16 warps x 32 rows, 4 independent loads per iter (good MLP)
#pragma unroll 4
    for (int q = 0; q < 32; q++) {
        int j = wid * 32 + q;
        int t = tjs[j];
        float v  = vjs[j];
        float vp = vpjs[j];
        float iz = izjs[j];
        const float* Ar = g_A  + oa + (size_t)t * ND;
        const float* Br = g_Bx + oa + (size_t)t * ND;
        float o0 = fmaf(vp, Ar[lane],      v * Br[lane])      * iz;
        float o1 = fmaf(vp, Ar[lane + 32], v * Br[lane + 32]) * iz;
        o0 = (o0 >= 0.f) ? o0 : ACVT * o0;
        o1 = (o1 >= 0.f) ? o1 : ACVT * o1;
        float* x2r = g_x2 + ((size_t)(b * NN + j) * HDIM) + h * ND;
        x2r[lane]      = o0;
        x2r[lane + 32] = o1;
    }
}

// -------- K5: f1/f2 = h2 @ a1o/a2o, plus max(f1) per object ------------------
__global__ __launch_bounds__(512) void k5_f(const float* __restrict__ a1o,
                                            const float* __restrict__ a2o)
{
    int b = blockIdx.x, k = threadIdx.x;
    __shared__ float s1[NO], s2[NO];
    __shared__ float red[512];
    if (k < NO) { s1[k] = a1o[k]; s2[k] = a2o[k]; }
    __syncthreads();
    const float4* hr = (const float4*)(g_h2 + (size_t)(b * NN + k) * NO);
    float f1 = 0.f, f2 = 0.f;
#pragma unroll
    for (int i = 0; i < NO / 4; i++) {
        float4 v = hr[i];
        f1 += v.x*s1[4*i] + v.y*s1[4*i+1] + v.z*s1[4*i+2] + v.w*s1[4*i+3];
        f2 += v.x*s2[4*i] + v.y*s2[4*i+1] + v.z*s2[4*i+2] + v.w*s2[4*i+3];
    }
    g_f1[b * NN + k] = f1;
    g_f2[b * NN + k] = f2;

    red[k] = f1;
    __syncthreads();
    for (int s = 256; s > 0; s >>= 1) {
        if (k < s) red[k] = fmaxf(red[k], red[k + s]);
        __syncthreads();
    }
    if (k == 0) g_maxf1[b] = red[0];
}

// -------- K6a: per-row max (closed form) + z_j, split over 128 blocks --------
__global__ __launch_bounds__(512) void k6a_rows()
{
    int b  = blockIdx.x;
    int jc = blockIdx.y;           // 0..3
    int tid = threadIdx.x;
    int jl = tid & 127, c = tid >> 7;    // 128 rows x 4 k-chunks
    __shared__ float f1s[NN];
    __shared__ float red[4][128];

    f1s[tid] = g_f1[b * NN + tid];
    __syncthreads();
    float maxf1 = g_maxf1[b];

    int j = jc * 128 + jl;
    float fj = g_f2[b * NN + j];
    float mraw = maxf1 + fj;
    float m = (mraw >= 0.f) ? mraw : ALPHA * mraw;   // = max_k leaky(f1k + f2j)

    float z = 0.f;
#pragma unroll 4
    for (int kk = c * 128; kk < c * 128 + 128; kk++) {
        float s = f1s[kk] + fj;
        s = (s >= 0.f) ? s : ALPHA * s;
        z += __expf(s - m);
    }
    red[c][jl] = z;
    __syncthreads();
    if (c == 0) {
        float zt = red[0][jl] + red[1][jl] + red[2][jl] + red[3][jl];
        g_ms [b * NN + j] = m;
        g_izv[b * NN + j] = 1.f / zt;
    }
}

// -------- K6b: w[k] = (1/N) sum_j att[j,k], split over 128 blocks ------------
__global__ __launch_bounds__(512) void k6b_cols()
{
    int b  = blockIdx.x;
    int kc = blockIdx.y;
    int tid = threadIdx.x;
    int kl = tid & 127, c = tid >> 7;
    __shared__ float f2s[NN], mss[NN], izs[NN];
    __shared__ float red[4][128];

    f2s[tid] = g_f2[b * NN + tid];
    mss[tid] = g_ms[b * NN + tid];
    izs[tid] = g_izv[b * NN + tid];
    __syncthreads();

    int k = kc * 128 + kl;
    float fk = g_f1[b * NN + k];
    float w = 0.f;
#pragma unroll 4
    for (int j = c * 128; j < c * 128 + 128; j++) {
        float s = fk + f2s[j];
        s = (s >= 0.f) ? s : ALPHA * s;
        w += __expf(s - mss[j]) * izs[j];
    }
    red[c][kl] = w;
    __syncthreads();
    if (c == 0) {
        float wt = red[0][kl] + red[1][kl] + red[2][kl] + red[3][kl];
        g_w[b * NN + k] = wt * (1.0f / (float)NN);
    }
}

// -------- K6c: weighted mean over rows + Linear + L2 normalize ---------------
__global__ __launch_bounds__(512) void k6c_final(const float* __restrict__ Wlin,
                                                 const float* __restrict__ blin,
                                                 float* __restrict__ out)
{
    int b = blockIdx.x, tid = threadIdx.x;
    int d = tid & 127, c = tid >> 7;     // 128 dims x 4 k-chunks
    __shared__ float ws[NN];
    __shared__ float red[4][NO];
    __shared__ float om[NO], ys[NO], nrm[4];

    ws[tid] = g_w[b * NN + tid];
    __syncthreads();

    float s = 0.f;
#pragma unroll 4
    for (int k = c * 128; k < c * 128 + 128; k++)
        s = fmaf(ws[k], g_h2[(size_t)(b * NN + k) * NO + d], s);
    red[c][d] = s;
    __syncthreads();
    if (c == 0) om[d] = red[0][d] + red[1][d] + red[2][d] + red[3][d];
    __syncthreads();

    if (tid < NO) {
        float y = blin[tid];
        const float* wr = Wlin + (size_t)tid * NO;
#pragma unroll 4
        for (int dd = 0; dd < NO; dd++) y = fmaf(om[dd], wr[dd], y);
        ys[tid] = y;
    }
    __syncthreads();

    if (tid < NO) {
        float v = ys[tid] * ys[tid];
#pragma unroll
        for (int st = 16; st > 0; st >>= 1) v += __shfl_down_sync(0xffffffffu, v, st);
        if ((tid & 31) == 0) nrm[tid >> 5] = v;
    }
    __syncthreads();
    if (tid == 0) {
        float t = nrm[0] + nrm[1] + nrm[2] + nrm[3];
        nrm[0] = fmaxf(sqrtf(t), 1e-12f);
    }
    __syncthreads();
    if (tid < NO) out[b * NO + tid] = ys[tid] / nrm[0];
}

// -----------------------------------------------------------------------------
extern "C" void kernel_launch(void* const* d_in, const int* in_sizes, int n_in,
                              void* d_out, int out_size)
{
    (void)in_sizes; (void)n_in; (void)out_size;
    const float* X    = (const float*)d_in[0];
    const float* Wt   = (const float*)d_in[1];
    const float* a1   = (const float*)d_in[2];
    const float* a2   = (const float*)d_in[3];
    const float* Wout = (const float*)d_in[4];
    const float* a1o  = (const float*)d_in[5];
    const float* a2o  = (const float*)d_in[6];
    const float* Wlin = (const float*)d_in[7];
    const float* blin = (const float*)d_in[8];
    float* out = (float*)d_out;

    gemm_nt<0><<<dim3(HDIM / 128, (BATCH * NN) / 128), 256>>>(X, Wt, BATCH * NN, HDIM, NF);
    k2_attn_prep<<<BATCH * NH, 256>>>(a1, a2);
    k3b_prefix<<<BATCH * NH, 512>>>();
    k3c_apply<<<BATCH * NH, 512>>>();
    gemm_nt<2><<<dim3(NO / 128, (BATCH * NN) / 128), 256>>>(nullptr, Wout, BATCH * NN, NO, HDIM);
    k5_f<<<BATCH, 512>>>(a1o, a2o);
    k6a_rows<<<dim3(BATCH, 4), 512>>>();
    k6b_cols<<<dim3(BATCH, 4), 512>>>();
    k6c_final<<<BATCH, 512>>>(Wlin, blin, out);
}